// round 8
// baseline (speedup 1.0000x reference)
#include <cuda_runtime.h>
#include <cuda_fp16.h>

#define BB 4
#define MM 128
#define LL 512
#define DD 768

#define LSPLIT 6
#define LMAX   86
#define APADU  132          // u32 row stride for sh_a (16B-aligned rows)
#define NEGH   0xFC00FC00u  // fp16x2 (-inf,-inf)
#define NDB    (DD / 128)   // 6 d-blocks

// fp16 partials [LSPLIT][B][M][D] = 4.7 MB static scratch (no allocs)
__device__ unsigned short g_scratch[LSPLIT * BB * MM * DD];
// per-(b,dblk) arrival counters; last block resets -> graph-replay safe
__device__ int g_cnt[BB * NDB];

#define SH_H_U32   (LMAX * 64)
#define SMEM_BYTES ((SH_H_U32 + LMAX * APADU) * (int)sizeof(unsigned int))  // ~66 KB

// scratch strides in uint4 units (16B = 8 fp16)
#define SP_STRIDE_U4 (BB * MM * DD / 8)     // 49152

__global__ __launch_bounds__(512, 1)
void mr_fused(const float* __restrict__ h, const int* __restrict__ mask,
              float* __restrict__ out)
{
    extern __shared__ unsigned int sm[];
    unsigned int* sh_h = sm;              // [l][64] fp16x2 (128 d)
    unsigned int* sh_a = sm + SH_H_U32;   // [l][APADU] additive splat (0 or -inf,-inf)
    __shared__ int sh_last;

    const int b    = blockIdx.z;
    const int dblk = blockIdx.x;
    const int d0   = dblk * 128;
    const int sp   = blockIdx.y;
    const int l0   = sp * 85 + (sp < 2 ? sp : 2);
    const int llen = 85 + (sp < 2 ? 1 : 0);

    const int tid  = threadIdx.x;
    const int lane = tid & 31;
    const int w    = tid >> 5;            // 16 warps; warp w -> m rows [8w, 8w+8)

    // ---- stage h tile: coalesced float4 LDG -> fp16x2 -> STS ----
    {
        const float4* hg = (const float4*)h + ((size_t)b * LL + l0) * (DD / 4) + (d0 >> 2);
        const int n = llen * 32;
        for (int idx = tid; idx < n; idx += 512) {
            const int l = idx >> 5, q = idx & 31;
            const float4 v = hg[(size_t)l * (DD / 4) + q];
            const half2 p0 = __float22half2_rn(make_float2(v.x, v.y));
            const half2 p1 = __float22half2_rn(make_float2(v.z, v.w));
            sh_h[l * 64 + q * 2]     = *(const unsigned int*)&p0;
            sh_h[l * 64 + q * 2 + 1] = *(const unsigned int*)&p1;
        }
    }
    // ---- stage mask transposed [l][m]; LDG coalesced over l ----
    for (int m = w; m < MM; m += 16) {
        const int* mg = mask + ((size_t)b * MM + m) * LL + l0;
        for (int lb = lane; lb < llen; lb += 32)
            sh_a[lb * APADU + m] = mg[lb] ? 0u : NEGH;
    }
    __syncthreads();

    // ---- accumulate: 8 m x 128 d (fp16x2) per warp ----
    const unsigned int ninf = NEGH;
    const half2 hninf = *(const half2*)&ninf;
    half2 acc[8][2];
#pragma unroll
    for (int i = 0; i < 8; ++i) { acc[i][0] = hninf; acc[i][1] = hninf; }

    const int mb = w * 8;
#pragma unroll 2
    for (int l = 0; l < llen; ++l) {
        const uint2 hv = *(const uint2*)&sh_h[l * 64 + lane * 2];
        const half2 h0 = *(const half2*)&hv.x;
        const half2 h1 = *(const half2*)&hv.y;
        const uint4 a0 = *(const uint4*)&sh_a[l * APADU + mb];      // uniform -> broadcast
        const uint4 a1 = *(const uint4*)&sh_a[l * APADU + mb + 4];
        unsigned int av[8] = {a0.x, a0.y, a0.z, a0.w, a1.x, a1.y, a1.z, a1.w};
#pragma unroll
        for (int i = 0; i < 8; ++i) {
            const half2 a = *(const half2*)&av[i];
            acc[i][0] = __hmax2(acc[i][0], __hadd2(h0, a));
            acc[i][1] = __hmax2(acc[i][1], __hadd2(h1, a));
        }
    }

    // ---- write fp16 partials [sp][b][m][d], coalesced 8B/thread ----
    unsigned short* op = g_scratch + (((size_t)sp * BB + b) * MM + mb) * DD + d0 + lane * 4;
#pragma unroll
    for (int i = 0; i < 8; ++i) {
        uint2 o;
        o.x = *(const unsigned int*)&acc[i][0];
        o.y = *(const unsigned int*)&acc[i][1];
        *(uint2*)(op + (size_t)i * DD) = o;
    }

    // ---- last-block combine for this (b, dblk) group ----
    __threadfence();
    __syncthreads();
    if (tid == 0) {
        const int old = atomicAdd(&g_cnt[b * NDB + dblk], 1);
        sh_last = (old == LSPLIT - 1) ? 1 : 0;
    }
    __syncthreads();
    if (!sh_last) return;
    if (tid == 0) g_cnt[b * NDB + dblk] = 0;   // reset for next graph replay
    __threadfence();                            // acquire

    // tile = 128 m x 128 d = 2048 uint4 (8 fp16 each); 4 per thread, MLP 6 loads
    const uint4* s = (const uint4*)g_scratch;
#pragma unroll
    for (int k = 0; k < 4; ++k) {
        const int e = k * 512 + tid;          // 0..2047
        const int m = e >> 4, q = e & 15;     // 16 uint4 per m-row (128 d)
        const size_t base = ((size_t)(b * MM + m) * DD + d0) / 8 + q;

        uint4 v[LSPLIT];
#pragma unroll
        for (int p = 0; p < LSPLIT; ++p)
            v[p] = s[(size_t)p * SP_STRIDE_U4 + base];

        half2 r0 = *(const half2*)&v[0].x;
        half2 r1 = *(const half2*)&v[0].y;
        half2 r2 = *(const half2*)&v[0].z;
        half2 r3 = *(const half2*)&v[0].w;
#pragma unroll
        for (int p = 1; p < LSPLIT; ++p) {
            r0 = __hmax2(r0, *(const half2*)&v[p].x);
            r1 = __hmax2(r1, *(const half2*)&v[p].y);
            r2 = __hmax2(r2, *(const half2*)&v[p].z);
            r3 = __hmax2(r3, *(const half2*)&v[p].w);
        }
        const float2 f0 = __half22float2(r0);
        const float2 f1 = __half22float2(r1);
        const float2 f2 = __half22float2(r2);
        const float2 f3 = __half22float2(r3);
        float4 o0, o1;
        o0.x = f0.x; o0.y = f0.y; o0.z = f1.x; o0.w = f1.y;
        o1.x = f2.x; o1.y = f2.y; o1.z = f3.x; o1.w = f3.y;
        float4* og = (float4*)out + base * 2;
        og[0] = o0;
        og[1] = o1;
    }
}

extern "C" void kernel_launch(void* const* d_in, const int* in_sizes, int n_in,
                              void* d_out, int out_size)
{
    const float* h    = (const float*)d_in[0];
    const int*   mask = (const int*)  d_in[1];
    float*       out  = (float*)d_out;

    cudaFuncSetAttribute(mr_fused,
                         cudaFuncAttributeMaxDynamicSharedMemorySize, SMEM_BYTES);

    dim3 grid(NDB, LSPLIT, BB);   // 6 x 6 x 4 = 144 blocks, occ 1
    mr_fused<<<grid, 512, SMEM_BYTES>>>(h, mask, out);
}

// round 9
// speedup vs baseline: 1.0107x; 1.0107x over previous
#include <cuda_runtime.h>
#include <cuda_fp16.h>

#define BB 4
#define MM 128
#define LL 512
#define DD 768

#define NEGH  0xFC00FC00u     // fp16x2 (-inf,-inf)
#define MW    22              // max mentions per block
#define APAD  24              // u32 row stride for sh_a (96B, 16B-aligned)
#define LCH   128             // l chunk per stage
#define NST   (LL / LCH)      // 4 stages

// smem: stage buffers (h: 128*64 u32, a: 128*24 u32 = 45KB)  OR  reduction (16*1408 u32 = 90.1KB)
#define SH_A_OFF   (LCH * 64)
#define RED_COLS   (MW * 64)                 // 1408 half2 columns per warp
#define SMEM_U32   (16 * RED_COLS)           // 22528 u32 = 90.1 KB (covers stage 11264 too)
#define SMEM_BYTES (SMEM_U32 * (int)sizeof(unsigned int))

__global__ __launch_bounds__(512, 1)
void mr_msplit(const float* __restrict__ h, const int* __restrict__ mask,
               float* __restrict__ out)
{
    extern __shared__ unsigned int sm[];
    unsigned int* sh_h = sm;               // [128 l][64] fp16x2 (128 d)
    unsigned int* sh_a = sm + SH_A_OFF;    // [128 l][APAD] additive splat

    const int b    = blockIdx.z;
    const int d0   = blockIdx.x * 128;
    const int mblk = blockIdx.y;
    const int m0   = mblk * 21 + (mblk < 2 ? mblk : 2);
    const int len  = 21 + (mblk < 2 ? 1 : 0);

    const int tid  = threadIdx.x;
    const int lane = tid & 31;
    const int w    = tid >> 5;             // 16 warps; warp w -> l = w (mod 16)

    const unsigned int ninf = NEGH;
    const half2 hninf = *(const half2*)&ninf;
    half2 acc[MW][2];
#pragma unroll
    for (int i = 0; i < MW; ++i) { acc[i][0] = hninf; acc[i][1] = hninf; }

    const float4* hg = (const float4*)h + ((size_t)b * LL) * (DD / 4) + (d0 >> 2);
    const int*    mg = mask + ((size_t)b * MM + m0) * LL;

    for (int st = 0; st < NST; ++st) {
        const int l0 = st * LCH;
        __syncthreads();
        // ---- stage h chunk: 128 l x 32 float4, coalesced ----
#pragma unroll
        for (int it = 0; it < (LCH * 32) / 512; ++it) {
            const int idx = it * 512 + tid;
            const int l = idx >> 5, q = idx & 31;
            const float4 v = hg[(size_t)(l0 + l) * (DD / 4) + q];
            const half2 p0 = __float22half2_rn(make_float2(v.x, v.y));
            const half2 p1 = __float22half2_rn(make_float2(v.z, v.w));
            uint2 o; o.x = *(const unsigned int*)&p0; o.y = *(const unsigned int*)&p1;
            *(uint2*)&sh_h[l * 64 + q * 2] = o;
        }
        // ---- stage mask splats [l][m], coalesced over l ----
        {
            const int l = tid & 127;
            for (int m = tid >> 7; m < MW; m += 4) {
                unsigned int val = 0u;
                if (m < len) val = mg[(size_t)m * LL + l0 + l] ? 0u : NEGH;
                sh_a[l * APAD + m] = val;
            }
        }
        __syncthreads();

        // ---- compute: warp w handles l = w + 16j, j=0..7; 22 m x 128 d ----
#pragma unroll
        for (int j = 0; j < LCH / 16; ++j) {
            const int ll = w + 16 * j;
            const uint2 hv = *(const uint2*)&sh_h[ll * 64 + lane * 2];
            const half2 h0 = *(const half2*)&hv.x;
            const half2 h1 = *(const half2*)&hv.y;
            const unsigned int* ar = &sh_a[ll * APAD];    // uniform -> broadcast
            const uint4 a0 = *(const uint4*)(ar);
            const uint4 a1 = *(const uint4*)(ar + 4);
            const uint4 a2 = *(const uint4*)(ar + 8);
            const uint4 a3 = *(const uint4*)(ar + 12);
            const uint4 a4 = *(const uint4*)(ar + 16);
            const uint4 a5 = *(const uint4*)(ar + 20);
            const unsigned int av[24] = {a0.x,a0.y,a0.z,a0.w, a1.x,a1.y,a1.z,a1.w,
                                         a2.x,a2.y,a2.z,a2.w, a3.x,a3.y,a3.z,a3.w,
                                         a4.x,a4.y,a4.z,a4.w, a5.x,a5.y,a5.z,a5.w};
#pragma unroll
            for (int i = 0; i < MW; ++i) {
                const half2 a = *(const half2*)&av[i];
                acc[i][0] = __hmax2(acc[i][0], __hadd2(h0, a));
                acc[i][1] = __hmax2(acc[i][1], __hadd2(h1, a));
            }
        }
    }

    // ---- cross-warp reduction: 16 partials per (m, d-half2) ----
    __syncthreads();                       // stage buffers dead; reuse as reduction buf
    {
        unsigned int* red = sm;            // [16 warps][MW*64]
#pragma unroll
        for (int i = 0; i < MW; ++i) {
            uint2 o;
            o.x = *(const unsigned int*)&acc[i][0];
            o.y = *(const unsigned int*)&acc[i][1];
            *(uint2*)&red[w * RED_COLS + i * 64 + lane * 2] = o;
        }
    }
    __syncthreads();

    {
        const unsigned int* red = sm;
#pragma unroll
        for (int k = 0; k < 3; ++k) {
            const int e = k * 512 + tid;           // 0..1407 half2 columns
            if (e < RED_COLS) {
                const int m = e >> 6, q = e & 63;
                unsigned int r0u = red[e];
                half2 r = *(const half2*)&r0u;
#pragma unroll
                for (int p = 1; p < 16; ++p) {
                    const unsigned int vu = red[p * RED_COLS + e];
                    r = __hmax2(r, *(const half2*)&vu);
                }
                if (m < len) {
                    const float2 f = __half22float2(r);
                    *(float2*)(out + ((size_t)b * MM + m0 + m) * DD + d0 + q * 2) = f;
                }
            }
        }
    }
}

extern "C" void kernel_launch(void* const* d_in, const int* in_sizes, int n_in,
                              void* d_out, int out_size)
{
    const float* h    = (const float*)d_in[0];
    const int*   mask = (const int*)  d_in[1];
    float*       out  = (float*)d_out;

    cudaFuncSetAttribute(mr_msplit,
                         cudaFuncAttributeMaxDynamicSharedMemorySize, SMEM_BYTES);

    dim3 grid(DD / 128, 6, BB);       // 6 d x 6 m x 4 b = 144 blocks
    mr_msplit<<<grid, 512, SMEM_BYTES>>>(h, mask, out);
}

// round 10
// speedup vs baseline: 1.2581x; 1.2448x over previous
#include <cuda_runtime.h>
#include <cuda_fp16.h>

#define BB 4
#define MM 128
#define LL 512
#define DD 768

#define LSPLIT 6
#define LMAX   86
#define APADU  132          // u32 row stride for sh_a (16B-aligned rows)
#define NEGH   0xFC00FC00u  // fp16x2 (-inf,-inf)

// fp16 partials [LSPLIT][B][M][D] = 4.7 MB static scratch (no allocs)
__device__ unsigned short g_scratch[LSPLIT * BB * MM * DD];

#define SH_H_U32   (LMAX * 64)
#define SMEM_BYTES ((SH_H_U32 + LMAX * APADU) * (int)sizeof(unsigned int))  // ~66 KB

__global__ __launch_bounds__(512, 1)
void mr_main(const float* __restrict__ h, const int* __restrict__ mask)
{
    extern __shared__ unsigned int sm[];
    unsigned int* sh_h = sm;              // [l][64] fp16x2 (128 d)
    unsigned int* sh_a = sm + SH_H_U32;   // [l][APADU] additive splat (0 or -inf,-inf)

    const int b    = blockIdx.z;
    const int d0   = blockIdx.x * 128;
    const int sp   = blockIdx.y;
    const int l0   = sp * 85 + (sp < 2 ? sp : 2);
    const int llen = 85 + (sp < 2 ? 1 : 0);

    const int tid  = threadIdx.x;
    const int lane = tid & 31;
    const int w    = tid >> 5;            // 16 warps; warp w -> m rows [8w, 8w+8)

    // ---- stage h tile: coalesced float4 LDG -> fp16x2 -> STS ----
    {
        const float4* hg = (const float4*)h + ((size_t)b * LL + l0) * (DD / 4) + (d0 >> 2);
        const int n = llen * 32;
        for (int idx = tid; idx < n; idx += 512) {
            const int l = idx >> 5, q = idx & 31;
            const float4 v = hg[(size_t)l * (DD / 4) + q];
            const half2 p0 = __float22half2_rn(make_float2(v.x, v.y));
            const half2 p1 = __float22half2_rn(make_float2(v.z, v.w));
            uint2 o; o.x = *(const unsigned int*)&p0; o.y = *(const unsigned int*)&p1;
            *(uint2*)&sh_h[l * 64 + q * 2] = o;
        }
    }
    // ---- stage mask transposed [l][m]; LDG coalesced over l ----
    for (int m = w; m < MM; m += 16) {
        const int* mg = mask + ((size_t)b * MM + m) * LL + l0;
        for (int lb = lane; lb < llen; lb += 32)
            sh_a[lb * APADU + m] = mg[lb] ? 0u : NEGH;
    }
    __syncthreads();

    // ---- accumulate: 8 m x 128 d (fp16x2) per warp; 2 l per iter, loads batched ----
    const unsigned int ninf = NEGH;
    const half2 hninf = *(const half2*)&ninf;
    half2 acc[8][2];
#pragma unroll
    for (int i = 0; i < 8; ++i) { acc[i][0] = hninf; acc[i][1] = hninf; }

    const int mb = w * 8;
    int l = 0;
    for (; l + 2 <= llen; l += 2) {
        // 6 independent LDS up-front
        const uint2 hva = *(const uint2*)&sh_h[(l + 0) * 64 + lane * 2];
        const uint2 hvb = *(const uint2*)&sh_h[(l + 1) * 64 + lane * 2];
        const uint4 a0  = *(const uint4*)&sh_a[(l + 0) * APADU + mb];
        const uint4 a1  = *(const uint4*)&sh_a[(l + 0) * APADU + mb + 4];
        const uint4 b0  = *(const uint4*)&sh_a[(l + 1) * APADU + mb];
        const uint4 b1  = *(const uint4*)&sh_a[(l + 1) * APADU + mb + 4];

        const half2 ha0 = *(const half2*)&hva.x, ha1 = *(const half2*)&hva.y;
        const half2 hb0 = *(const half2*)&hvb.x, hb1 = *(const half2*)&hvb.y;
        const unsigned int av[8] = {a0.x,a0.y,a0.z,a0.w, a1.x,a1.y,a1.z,a1.w};
        const unsigned int bv[8] = {b0.x,b0.y,b0.z,b0.w, b1.x,b1.y,b1.z,b1.w};
#pragma unroll
        for (int i = 0; i < 8; ++i) {
            const half2 aa = *(const half2*)&av[i];
            const half2 ab = *(const half2*)&bv[i];
            acc[i][0] = __hmax2(__hmax2(acc[i][0], __hadd2(ha0, aa)), __hadd2(hb0, ab));
            acc[i][1] = __hmax2(__hmax2(acc[i][1], __hadd2(ha1, aa)), __hadd2(hb1, ab));
        }
    }
    if (l < llen) {   // tail (llen odd: 85)
        const uint2 hv = *(const uint2*)&sh_h[l * 64 + lane * 2];
        const uint4 a0 = *(const uint4*)&sh_a[l * APADU + mb];
        const uint4 a1 = *(const uint4*)&sh_a[l * APADU + mb + 4];
        const half2 h0 = *(const half2*)&hv.x, h1 = *(const half2*)&hv.y;
        const unsigned int av[8] = {a0.x,a0.y,a0.z,a0.w, a1.x,a1.y,a1.z,a1.w};
#pragma unroll
        for (int i = 0; i < 8; ++i) {
            const half2 a = *(const half2*)&av[i];
            acc[i][0] = __hmax2(acc[i][0], __hadd2(h0, a));
            acc[i][1] = __hmax2(acc[i][1], __hadd2(h1, a));
        }
    }

    // ---- write fp16 partials [sp][b][m][d], coalesced 8B/thread ----
    unsigned short* op = g_scratch + (((size_t)sp * BB + b) * MM + mb) * DD + d0 + lane * 4;
#pragma unroll
    for (int i = 0; i < 8; ++i) {
        uint2 o;
        o.x = *(const unsigned int*)&acc[i][0];
        o.y = *(const unsigned int*)&acc[i][1];
        *(uint2*)(op + (size_t)i * DD) = o;
    }
}

#define TOTU4 (BB * MM * DD / 8)    // 49152 uint4 (8 fp16 each)

__global__ __launch_bounds__(256, 1)
void mr_combine(float* __restrict__ out)
{
    const int t = blockIdx.x * 256 + threadIdx.x;    // 0..49151
    const uint4* s = (const uint4*)g_scratch;

    uint4 v[LSPLIT];
#pragma unroll
    for (int sp = 0; sp < LSPLIT; ++sp)              // MLP 6 x LDG.128
        v[sp] = s[(size_t)sp * TOTU4 + t];

    half2 r0 = *(const half2*)&v[0].x;
    half2 r1 = *(const half2*)&v[0].y;
    half2 r2 = *(const half2*)&v[0].z;
    half2 r3 = *(const half2*)&v[0].w;
#pragma unroll
    for (int sp = 1; sp < LSPLIT; ++sp) {
        r0 = __hmax2(r0, *(const half2*)&v[sp].x);
        r1 = __hmax2(r1, *(const half2*)&v[sp].y);
        r2 = __hmax2(r2, *(const half2*)&v[sp].z);
        r3 = __hmax2(r3, *(const half2*)&v[sp].w);
    }
    const float2 f0 = __half22float2(r0);
    const float2 f1 = __half22float2(r1);
    const float2 f2 = __half22float2(r2);
    const float2 f3 = __half22float2(r3);
    float4 o0, o1;
    o0.x = f0.x; o0.y = f0.y; o0.z = f1.x; o0.w = f1.y;
    o1.x = f2.x; o1.y = f2.y; o1.z = f3.x; o1.w = f3.y;
    float4* og = (float4*)out + (size_t)t * 2;
    og[0] = o0;
    og[1] = o1;
}

extern "C" void kernel_launch(void* const* d_in, const int* in_sizes, int n_in,
                              void* d_out, int out_size)
{
    const float* h    = (const float*)d_in[0];
    const int*   mask = (const int*)  d_in[1];
    float*       out  = (float*)d_out;

    cudaFuncSetAttribute(mr_main,
                         cudaFuncAttributeMaxDynamicSharedMemorySize, SMEM_BYTES);

    dim3 grid(DD / 128, LSPLIT, BB);      // 6 x 6 x 4 = 144 blocks, occ 1
    mr_main<<<grid, 512, SMEM_BYTES>>>(h, mask);
    mr_combine<<<TOTU4 / 256, 256>>>(out);   // 192 blocks
}